// round 12
// baseline (speedup 1.0000x reference)
#include <cuda_runtime.h>
#include <cuda_bf16.h>
#include <math.h>
#include <stdint.h>

constexpr int Bb = 4;
constexpr int Np = 20000;
constexpr int Cc = 256;
constexpr int NS = 1024;
constexpr int NV = 300;

// output offsets (float32 elements), reference return order, row-major flatten
constexpr size_t OFF0 = 0;        // objectness (B,2,N)
constexpr size_t OFF1 = 160000;   // graspness (B,N)
constexpr size_t OFF2 = 240000;   // graspable_xyz (B,NS,3)
constexpr size_t OFF3 = 252288;   // graspable_inds (B,NS)
constexpr size_t OFF4 = 256384;   // graspable_features (B,C,NS)
constexpr size_t OFF5 = 1304960;  // fp2_graspness (B,NS)
constexpr size_t OFF6 = 1309056;  // vp_xyz (B,NS,3)
constexpr size_t OFF7 = 1321344;  // top_view_inds (B,NS)
constexpr size_t OFF8 = 1325440;  // vp_rot (B,NS,3,3)

__device__ unsigned char g_mask[Bb * Np];
__device__ int    g_cidx[Bb][Np];
__device__ float4 g_cxyz[Bb][Np];
__device__ int    g_sel[Bb][NS];
__device__ unsigned long long g_W1t[Cc * Cc];
__device__ unsigned long long g_c1wt[Cc * Cc];

// ---------- f32x2 helpers (per-lane bit-identical to scalar __f*_rn) ----------
__device__ __forceinline__ unsigned long long pk2(float a, float b) {
    unsigned long long r;
    asm("mov.b64 %0, {%1, %2};" : "=l"(r) : "f"(a), "f"(b));
    return r;
}
__device__ __forceinline__ void up2(unsigned long long v, float& a, float& b) {
    asm("mov.b64 {%0, %1}, %2;" : "=f"(a), "=f"(b) : "l"(v));
}
__device__ __forceinline__ unsigned long long fma2(unsigned long long a, unsigned long long b,
                                                   unsigned long long c) {
    unsigned long long d;
    asm("fma.rn.f32x2 %0, %1, %2, %3;" : "=l"(d) : "l"(a), "l"(b), "l"(c));
    return d;
}
__device__ __forceinline__ unsigned long long add2(unsigned long long a, unsigned long long b) {
    unsigned long long d;
    asm("add.rn.f32x2 %0, %1, %2;" : "=l"(d) : "l"(a), "l"(b));
    return d;
}
__device__ __forceinline__ unsigned long long mul2(unsigned long long a, unsigned long long b) {
    unsigned long long d;
    asm("mul.rn.f32x2 %0, %1, %2;" : "=l"(d) : "l"(a), "l"(b));
    return d;
}
__device__ __forceinline__ void cpa16(unsigned s, const void* g) {
    asm volatile("cp.async.cg.shared.global [%0], [%1], 16;" :: "r"(s), "l"(g) : "memory");
}

// ================= prepass: transpose + duplicate weights =================
__global__ void k_prep(const float* __restrict__ W1, const float* __restrict__ c1w) {
    int i = blockIdx.x * 256 + threadIdx.x;
    int co = i >> 8, ci = i & 255;
    float w = W1[i];
    g_W1t[ci * 256 + co] = pk2(w, w);
    float v = c1w[i];
    g_c1wt[ci * 256 + co] = pk2(v, v);
}

// ================= wide gather: graspable_features =================
__global__ __launch_bounds__(256) void k_gather(const float* __restrict__ F,
                                                float* __restrict__ out) {
    int i = blockIdx.x * 256 + threadIdx.x;
    int s = i & (NS - 1);
    int c = (i >> 10) & 255;
    int b = i >> 18;
    int idx = g_sel[b][s];
    out[OFF4 + (size_t)b * Cc * NS + (size_t)c * NS + s] =
        F[(size_t)b * Cc * Np + (size_t)c * Np + idx];
}

// ---------- GEMM tile constants (64 points x 256 co per block) ----------
constexpr int TPTS = 64;
constexpr int SM_FSM  = 0;       // 16384 floats
constexpr int SM_WBUF = 16384;   // 2 bufs x 2048 u64
constexpr int SM_W2   = 24576;   // 768
constexpr int SM_B2   = 25344;   // 4
constexpr int SM1_FLOATS = 25348;
constexpr int SM_VSM = 25348;    // 900
constexpr int SM_VPS = 26248;    // 192
constexpr int SM4_FLOATS = 26440;

__device__ __forceinline__ void gemm_tile(const unsigned long long* __restrict__ Wt,
                                          float* sm, int tid, int tx, int ty,
                                          float acc[8][8]) {
    float* fsm = sm + SM_FSM;
    unsigned long long* wsmU = reinterpret_cast<unsigned long long*>(sm + SM_WBUF);
    unsigned wbase = (unsigned)__cvta_generic_to_shared(wsmU);

    unsigned long long acc2[8][4];
#pragma unroll
    for (int j = 0; j < 8; ++j)
#pragma unroll
        for (int q = 0; q < 4; ++q) acc2[j][q] = 0ull;

    {
        const char* src = (const char*)Wt;
#pragma unroll
        for (int r = 0; r < 4; ++r)
            cpa16(wbase + (r * 256 + tid) * 16, src + (r * 256 + tid) * 16);
        asm volatile("cp.async.commit_group;" ::: "memory");
    }

    for (int ck = 0; ck < 32; ++ck) {
        asm volatile("cp.async.wait_group 0;" ::: "memory");
        __syncthreads();
        if (ck < 31) {
            const char* src = (const char*)(Wt + (ck + 1) * 2048);
            unsigned d = wbase + ((ck + 1) & 1) * 16384;
#pragma unroll
            for (int r = 0; r < 4; ++r)
                cpa16(d + (r * 256 + tid) * 16, src + (r * 256 + tid) * 16);
            asm volatile("cp.async.commit_group;" ::: "memory");
        }
        const unsigned long long* wbuf = wsmU + (ck & 1) * 2048;
#pragma unroll
        for (int ci = 0; ci < 8; ++ci) {
            const ulonglong2* wp =
                reinterpret_cast<const ulonglong2*>(wbuf + ci * 256 + 8 * ty);
            ulonglong2 w0 = wp[0], w1 = wp[1], w2 = wp[2], w3 = wp[3];
            const ulonglong2* fq = reinterpret_cast<const ulonglong2*>(
                fsm + (ck * 8 + ci) * TPTS + 8 * tx);
            ulonglong2 q0 = fq[0], q1 = fq[1];
            unsigned long long f2[4] = {q0.x, q0.y, q1.x, q1.y};
            unsigned long long wd[8] = {w0.x, w0.y, w1.x, w1.y, w2.x, w2.y, w3.x, w3.y};
#pragma unroll
            for (int j = 0; j < 8; ++j)
#pragma unroll
                for (int q = 0; q < 4; ++q) acc2[j][q] = fma2(f2[q], wd[j], acc2[j][q]);
        }
    }
    __syncthreads();
#pragma unroll
    for (int j = 0; j < 8; ++j)
#pragma unroll
        for (int q = 0; q < 4; ++q) up2(acc2[j][q], acc[j][2 * q], acc[j][2 * q + 1]);
}

__device__ __forceinline__ void bn_params(const float* gg, const float* be, const float* mm,
                                          const float* vv, const float* b1, int ty,
                                          float sc[8], float bias2[8], float b1v[8]) {
#pragma unroll
    for (int j = 0; j < 8; ++j) {
        int co = 8 * ty + j;
        float s = __fdiv_rn(gg[co], sqrtf(__fadd_rn(vv[co], 1e-5f)));
        sc[j] = s;
        bias2[j] = __fsub_rn(be[co], __fmul_rn(mm[co], s));
        b1v[j] = b1[co];
    }
}

__device__ __forceinline__ void head3(const float* w2sm, float acc[8][8],
                                      const float sc[8], const float bias2[8],
                                      const float b1v[8], int ty, float p3[3][8]) {
#pragma unroll
    for (int j = 0; j < 8; ++j) {
        int co = 8 * ty + j;
        float w0 = w2sm[co], w1c = w2sm[256 + co], w2c = w2sm[512 + co];
#pragma unroll
        for (int p = 0; p < 8; ++p) {
            float t = __fadd_rn(acc[j][p], b1v[j]);
            t = __fmul_rn(t, sc[j]);
            t = __fadd_rn(t, bias2[j]);
            float h = fmaxf(t, 0.f);
            p3[0][p] = fmaf(w0, h, p3[0][p]);
            p3[1][p] = fmaf(w1c, h, p3[1][p]);
            p3[2][p] = fmaf(w2c, h, p3[2][p]);
        }
    }
}

__device__ __forceinline__ void reduce3(float* red, float p3[3][8], int tx, int ty) {
#pragma unroll
    for (int k = 0; k < 3; ++k)
#pragma unroll
        for (int p = 0; p < 8; ++p) red[ty * 192 + k * 64 + 8 * tx + p] = p3[k][p];
    __syncthreads();
    for (int s = 16; s >= 1; s >>= 1) {
        if (ty < s) {
#pragma unroll
            for (int k = 0; k < 3; ++k)
#pragma unroll
                for (int p = 0; p < 8; ++p)
                    red[ty * 192 + k * 64 + 8 * tx + p] +=
                        red[(ty + s) * 192 + k * 64 + 8 * tx + p];
        }
        __syncthreads();
    }
}

// ================= K1 =================
__global__ __launch_bounds__(256, 2) void k_gemm_mask(
    const float* __restrict__ F, const float* __restrict__ b1,
    const float* __restrict__ gg, const float* __restrict__ be, const float* __restrict__ mm,
    const float* __restrict__ vv, const float* __restrict__ W2, const float* __restrict__ b2,
    float* __restrict__ out) {
    extern __shared__ float sm[];
    float* fsm  = sm + SM_FSM;
    float* w2sm = sm + SM_W2;
    float* b2sm = sm + SM_B2;

    int b = blockIdx.y, n0 = blockIdx.x * TPTS, tid = threadIdx.x;
    int tx = tid & 7, ty = tid >> 3;

    for (int t = tid; t < 768; t += 256) w2sm[t] = W2[t];
    if (tid < 3) b2sm[tid] = b2[tid];

    const float* Fb = F + (size_t)b * Cc * Np;
    for (int idx = tid; idx < 256 * TPTS; idx += 256) {
        int c = idx >> 6, p = idx & 63;
        int n = n0 + p;
        fsm[idx] = (n < Np) ? Fb[(size_t)c * Np + n] : 0.f;
    }
    __syncthreads();

    float acc[8][8];
    gemm_tile(g_W1t, sm, tid, tx, ty, acc);

    float sc[8], bias2[8], b1v[8];
    bn_params(gg, be, mm, vv, b1, ty, sc, bias2, b1v);

    float p3[3][8];
#pragma unroll
    for (int k = 0; k < 3; ++k)
#pragma unroll
        for (int p = 0; p < 8; ++p) p3[k][p] = 0.f;
    head3(w2sm, acc, sc, bias2, b1v, ty, p3);

    float* red = fsm;
    reduce3(red, p3, tx, ty);

    if (ty == 0) {
#pragma unroll
        for (int p = 0; p < 8; ++p) {
            int pt = 8 * tx + p;
            int n = n0 + pt;
            if (n < Np) {
                float s0 = __fadd_rn(red[pt], b2sm[0]);
                float s1 = __fadd_rn(red[64 + pt], b2sm[1]);
                float gr = __fadd_rn(red[128 + pt], b2sm[2]);
                out[OFF0 + (size_t)b * 2 * Np + n] = s0;
                out[OFF0 + (size_t)b * 2 * Np + Np + n] = s1;
                out[OFF1 + (size_t)b * Np + n] = gr;
                g_mask[b * Np + n] = (unsigned char)((s1 > s0) && (gr > 0.1f));
            }
        }
    }
}

// ================= K3: 256-thread, 8192-pts-in-registers FPS =================
constexpr int FT    = 256;        // threads (8 warps)
constexpr int RPAIR = 16;         // 16 pairs -> 32 reg slots = 8192 pts
constexpr int RREG  = RPAIR * 2 * FT;   // 8192
constexpr int SMPTS = 10240;      // xyz slots in smem (40 slots of 256)
constexpr int NDSM  = Np - RREG;  // 11808 smem dists for idx >= RREG
// smem byte offsets
constexpr int FP_SXYZ  = 0;           // 163840
constexpr int FP_DIST  = 163840;      // 47232
constexpr int FP_SEQ   = 211072;      // 4096
constexpr int FP_REDD  = 215168;      // 2x8 u32 = 64
constexpr int FP_REDI  = 215232;      // 64
constexpr int FP_WCNT  = 215296;      // 64
constexpr int FP_SBASE = 215360;      // 64
constexpr int FP_BYTES = 215424;

__global__ __launch_bounds__(FT, 1) void k_fps(const float* __restrict__ xyz,
                                               float* __restrict__ out) {
    extern __shared__ char smc[];
    float4*   sxyz  = (float4*)(smc + FP_SXYZ);
    float*    distSm= (float*)(smc + FP_DIST);
    int*      seq   = (int*)(smc + FP_SEQ);
    unsigned* redD  = (unsigned*)(smc + FP_REDD);
    int*      redI  = (int*)(smc + FP_REDI);
    int*      wcnt  = (int*)(smc + FP_WCNT);
    int*      sBase = (int*)(smc + FP_SBASE);

    int b = blockIdx.x, tid = threadIdx.x, lane = tid & 31, wid = tid >> 5;
    const float* xb = xyz + (size_t)b * Np * 3;

    if (tid == 0) sBase[0] = 0;
    __syncthreads();

    // stable stream compaction of masked points
    for (int c0 = 0; c0 < Np; c0 += FT) {
        int n = c0 + tid;
        bool mk = (n < Np) && g_mask[b * Np + n];
        unsigned bal = __ballot_sync(0xffffffffu, mk);
        int pre = __popc(bal & ((1u << lane) - 1u));
        if (lane == 0) wcnt[wid] = __popc(bal);
        __syncthreads();
        if (tid == 0) {
            int a = sBase[0];
            for (int w = 0; w < FT / 32; ++w) { int t = wcnt[w]; wcnt[w] = a; a += t; }
            sBase[0] = a;
        }
        __syncthreads();
        if (mk) {
            int pos = wcnt[wid] + pre;
            float4 p = make_float4(xb[n * 3], xb[n * 3 + 1], xb[n * 3 + 2], 0.f);
            g_cidx[b][pos] = n;
            g_cxyz[b][pos] = p;
            if (pos < SMPTS) sxyz[pos] = p;
        }
        __syncthreads();
    }
    int M = sBase[0];
    const float NEGINF = __int_as_float(0xff800000);

    float rd[2 * RPAIR];
#pragma unroll
    for (int k = 0; k < 2 * RPAIR; ++k)
        rd[k] = (k * FT + tid < M) ? 1e10f : NEGINF;
    unsigned long long rxp[RPAIR], ryp[RPAIR], rzp[RPAIR];
#pragma unroll
    for (int m = 0; m < RPAIR; ++m) {  // stale reads beyond M guarded by rd=NEGINF
        float4 p0 = sxyz[(2 * m) * FT + tid];
        float4 p1 = sxyz[(2 * m + 1) * FT + tid];
        rxp[m] = pk2(p0.x, p1.x);
        ryp[m] = pk2(p0.y, p1.y);
        rzp[m] = pk2(p0.z, p1.z);
    }
    for (int it = tid; it < NDSM; it += FT)
        distSm[it] = (RREG + it < M) ? 1e10f : NEGINF;
    if (tid == 0) seq[0] = 0;
    __syncthreads();

    int kmax = (M + FT - 1) / FT;
    if (kmax > SMPTS / FT) kmax = SMPTS / FT;

    if (M > 0) {
        float4 p0 = sxyz[0];
        float px = p0.x, py = p0.y, pz = p0.z;
        for (int s = 1; s < NS; ++s) {
            unsigned long long ncx = pk2(-px, -px);
            unsigned long long ncy = pk2(-py, -py);
            unsigned long long ncz = pk2(-pz, -pz);
            float best = NEGINF;
            int bi = 0x7fffffff;
#pragma unroll
            for (int m = 0; m < RPAIR; ++m) {
                if (2 * m * FT < M) {  // uniform branch
                    unsigned long long dx2 = add2(rxp[m], ncx);
                    unsigned long long dy2 = add2(ryp[m], ncy);
                    unsigned long long dz2 = add2(rzp[m], ncz);
                    unsigned long long d2 = add2(
                        add2(mul2(dx2, dx2), mul2(dy2, dy2)), mul2(dz2, dz2));
                    float da, db;
                    up2(d2, da, db);
                    float nda = fminf(rd[2 * m], da);
                    rd[2 * m] = nda;
                    if (nda > best) { best = nda; bi = (2 * m) * FT + tid; }
                    float ndb = fminf(rd[2 * m + 1], db);
                    rd[2 * m + 1] = ndb;
                    if (ndb > best) { best = ndb; bi = (2 * m + 1) * FT + tid; }
                }
            }
            for (int k = 2 * RPAIR; k < kmax; ++k) {  // smem slots (rare)
                int i = k * FT + tid;
                float4 p = sxyz[i];
                float dx = __fsub_rn(p.x, px);
                float dy = __fsub_rn(p.y, py);
                float dz = __fsub_rn(p.z, pz);
                float d = __fadd_rn(__fadd_rn(__fmul_rn(dx, dx), __fmul_rn(dy, dy)),
                                    __fmul_rn(dz, dz));
                float nd = fminf(distSm[i - RREG], d);
                distSm[i - RREG] = nd;
                if (nd > best) { best = nd; bi = i; }
            }
            for (int i = SMPTS + tid; i < M; i += FT) {  // global overflow (rarer)
                float4 p = g_cxyz[b][i];
                float dx = __fsub_rn(p.x, px);
                float dy = __fsub_rn(p.y, py);
                float dz = __fsub_rn(p.z, pz);
                float d = __fadd_rn(__fadd_rn(__fmul_rn(dx, dx), __fmul_rn(dy, dy)),
                                    __fmul_rn(dz, dz));
                float nd = fminf(distSm[i - RREG], d);
                distSm[i - RREG] = nd;
                if (nd > best) { best = nd; bi = i; }
            }
            // REDUX two-level argmax: dist-bits max (u32, dists >= 0), ties -> min idx
            unsigned db = (bi == 0x7fffffff) ? 0u : __float_as_uint(best);
            unsigned mx = __reduce_max_sync(0xffffffffu, db);
            int cand = (db == mx) ? bi : 0x7fffffff;
            int wmin = __reduce_min_sync(0xffffffffu, cand);
            int buf = (s & 1) * 8;
            if (lane == 0) { redD[buf + wid] = mx; redI[buf + wid] = wmin; }
            __syncthreads();
            unsigned db2 = (lane < 8) ? redD[buf + lane] : 0u;
            int bi2 = (lane < 8) ? redI[buf + lane] : 0x7fffffff;
            unsigned mx2 = __reduce_max_sync(0xffffffffu, db2);
            int cand2 = (db2 == mx2) ? bi2 : 0x7fffffff;
            int win = __reduce_min_sync(0xffffffffu, cand2);
            if (tid == 0) seq[s] = win;
            float4 pw = (win < SMPTS) ? sxyz[win] : g_cxyz[b][win];
            px = pw.x; py = pw.y; pz = pw.z;
        }
    }
    __syncthreads();

    // epilogue: inds / xyz / fp2_graspness
    for (int t = tid; t < NS; t += FT) {
        int orig; float x, y, z;
        if (M > 0) {
            int c = seq[t];
            orig = g_cidx[b][c];
            float4 p = g_cxyz[b][c];
            x = p.x; y = p.y; z = p.z;
        } else {
            orig = 0; x = xb[0]; y = xb[1]; z = xb[2];
        }
        out[OFF3 + (size_t)b * NS + t] = (float)orig;
        out[OFF2 + (size_t)b * NS * 3 + t * 3 + 0] = x;
        out[OFF2 + (size_t)b * NS * 3 + t * 3 + 1] = y;
        out[OFF2 + (size_t)b * NS * 3 + t * 3 + 2] = z;
        out[OFF5 + (size_t)b * NS + t] = out[OFF1 + (size_t)b * Np + orig];
        g_sel[b][t] = orig;
    }
}

// ================= K4 (reads gathered features coalesced from out[OFF4]) ========
__global__ __launch_bounds__(256, 2) void k_view(
    const float* __restrict__ b1,
    const float* __restrict__ gg, const float* __restrict__ be, const float* __restrict__ mm,
    const float* __restrict__ vv, const float* __restrict__ W2, const float* __restrict__ b2,
    float* __restrict__ out) {
    extern __shared__ float sm[];
    float* fsm  = sm + SM_FSM;
    float* w2sm = sm + SM_W2;
    float* b2sm = sm + SM_B2;
    float* vsm  = sm + SM_VSM;
    float* vps  = sm + SM_VPS;

    int b = blockIdx.y, s0 = blockIdx.x * TPTS, tid = threadIdx.x;
    int tx = tid & 7, ty = tid >> 3;

    for (int t = tid; t < 768; t += 256) w2sm[t] = W2[t];
    if (tid < 3) b2sm[tid] = b2[tid];

    for (int i = tid; i < NV; i += 256) {
        double z = (2.0 * (double)i + 1.0) / (double)NV - 1.0;
        double r = sqrt(fmax(1.0 - z * z, 0.0));
        double phi = (sqrt(5.0) - 1.0) / 2.0;
        double ang = (2.0 * 3.14159265358979323846) * (double)i * phi;
        float x = (float)(r * cos(ang)), y = (float)(r * sin(ang)), zf = (float)z;
        float nr2 = __fadd_rn(__fadd_rn(__fmul_rn(x, x), __fmul_rn(y, y)), __fmul_rn(zf, zf));
        float nr = fmaxf(sqrtf(nr2), 1e-8f);
        vsm[i * 3 + 0] = __fdiv_rn(x, nr);
        vsm[i * 3 + 1] = __fdiv_rn(y, nr);
        vsm[i * 3 + 2] = __fdiv_rn(zf, nr);
    }

    const float* Gb = out + OFF4 + (size_t)b * Cc * NS;
    for (int idx = tid; idx < 256 * 16; idx += 256) {
        int c = idx >> 4, q = idx & 15;
        reinterpret_cast<float4*>(fsm + c * 64)[q] =
            *reinterpret_cast<const float4*>(Gb + (size_t)c * NS + s0 + 4 * q);
    }
    __syncthreads();

    float acc[8][8];
    gemm_tile(g_c1wt, sm, tid, tx, ty, acc);

    float sc[8], bias2[8], b1v[8];
    bn_params(gg, be, mm, vv, b1, ty, sc, bias2, b1v);

    float p3[3][8];
#pragma unroll
    for (int k = 0; k < 3; ++k)
#pragma unroll
        for (int p = 0; p < 8; ++p) p3[k][p] = 0.f;
    head3(w2sm, acc, sc, bias2, b1v, ty, p3);

    float* red = fsm;
    reduce3(red, p3, tx, ty);

    if (ty == 0) {
#pragma unroll
        for (int p = 0; p < 8; ++p) {
            int pt = 8 * tx + p;
            int s = s0 + pt;
            float v0 = __fadd_rn(red[pt], b2sm[0]);
            float v1 = __fadd_rn(red[64 + pt], b2sm[1]);
            float v2 = __fadd_rn(red[128 + pt], b2sm[2]);
            out[OFF6 + (size_t)b * NS * 3 + (size_t)s * 3 + 0] = v0;
            out[OFF6 + (size_t)b * NS * 3 + (size_t)s * 3 + 1] = v1;
            out[OFF6 + (size_t)b * NS * 3 + (size_t)s * 3 + 2] = v2;
            vps[pt * 3 + 0] = v0; vps[pt * 3 + 1] = v1; vps[pt * 3 + 2] = v2;
        }
    }
    __syncthreads();

    if (tid < TPTS) {
        int s = s0 + tid;
        float vx = vps[tid * 3], vy = vps[tid * 3 + 1], vz = vps[tid * 3 + 2];
        float n2 = __fadd_rn(__fadd_rn(__fmul_rn(vx, vx), __fmul_rn(vy, vy)), __fmul_rn(vz, vz));
        float nr = fmaxf(sqrtf(n2), 1e-8f);
        float ax_ = __fdiv_rn(vx, nr), ay_ = __fdiv_rn(vy, nr), az_ = __fdiv_rn(vz, nr);
        float best = __int_as_float(0xff800000);
        int bi = 0;
        for (int v = 0; v < NV; ++v) {
            float c = __fadd_rn(__fadd_rn(__fmul_rn(ax_, vsm[v * 3]),
                                          __fmul_rn(ay_, vsm[v * 3 + 1])),
                                __fmul_rn(az_, vsm[v * 3 + 2]));
            if (c > best) { best = c; bi = v; }
        }
        out[OFF7 + (size_t)b * NS + s] = (float)bi;

        float tx0 = -vx, tx1 = -vy, tx2 = -vz;
        float ay0 = -tx1, ay1 = tx0, ay2 = 0.f;
        float s2 = ay0 * ay0 + ay1 * ay1;
        if (s2 == 0.f) { ay0 = 0.f; ay1 = 1.f; ay2 = 0.f; }
        float an = sqrtf(tx0 * tx0 + tx1 * tx1 + tx2 * tx2);
        float nx0 = tx0 / an, nx1 = tx1 / an, nx2 = tx2 / an;
        float bn = sqrtf(ay0 * ay0 + ay1 * ay1 + ay2 * ay2);
        float ny0 = ay0 / bn, ny1 = ay1 / bn, ny2 = ay2 / bn;
        float nz0 = nx1 * ny2 - nx2 * ny1;
        float nz1 = nx2 * ny0 - nx0 * ny2;
        float nz2 = nx0 * ny1 - nx1 * ny0;
        size_t base = OFF8 + ((size_t)b * NS + s) * 9;
        out[base + 0] = nx0; out[base + 1] = ny0; out[base + 2] = nz0;
        out[base + 3] = nx1; out[base + 4] = ny1; out[base + 5] = nz1;
        out[base + 6] = nx2; out[base + 7] = ny2; out[base + 8] = nz2;
    }
}

// ================= launch (robust input-order detection) =================
extern "C" void kernel_launch(void* const* d_in, const int* in_sizes, int n_in,
                              void* d_out, int out_size) {
    const float *xyz, *F, *w1, *b1, *gg, *be, *mm, *vv, *w2, *b2;
    const float *c1w, *c1b, *bng, *bnb, *bnm, *bnv, *c2w, *c2b;

    int imax = 0;
    for (int i = 1; i < n_in; ++i)
        if (in_sizes[i] > in_sizes[imax]) imax = i;

    if (imax == 1) {  // dict-insertion / signature order
        xyz = (const float*)d_in[0];  F   = (const float*)d_in[1];
        w1  = (const float*)d_in[2];  b1  = (const float*)d_in[3];
        gg  = (const float*)d_in[4];  be  = (const float*)d_in[5];
        mm  = (const float*)d_in[6];  vv  = (const float*)d_in[7];
        w2  = (const float*)d_in[8];  b2  = (const float*)d_in[9];
        c1w = (const float*)d_in[10]; c1b = (const float*)d_in[11];
        bng = (const float*)d_in[12]; bnb = (const float*)d_in[13];
        bnm = (const float*)d_in[14]; bnv = (const float*)d_in[15];
        c2w = (const float*)d_in[16]; c2b = (const float*)d_in[17];
    } else {          // alphabetical order
        bnb = (const float*)d_in[0];  bng = (const float*)d_in[1];
        bnm = (const float*)d_in[2];  bnv = (const float*)d_in[3];
        c1b = (const float*)d_in[4];  c1w = (const float*)d_in[5];
        c2b = (const float*)d_in[6];  c2w = (const float*)d_in[7];
        b1  = (const float*)d_in[8];  b2  = (const float*)d_in[9];
        be  = (const float*)d_in[10]; gg  = (const float*)d_in[11];
        mm  = (const float*)d_in[12]; vv  = (const float*)d_in[13];
        w1  = (const float*)d_in[14]; w2  = (const float*)d_in[15];
        F   = (const float*)d_in[16]; xyz = (const float*)d_in[17];
    }
    float* out = (float*)d_out;

    const int SM1 = SM1_FLOATS * 4;
    const int SM3 = FP_BYTES;
    const int SM4 = SM4_FLOATS * 4;
    cudaFuncSetAttribute(k_gemm_mask, cudaFuncAttributeMaxDynamicSharedMemorySize, SM1);
    cudaFuncSetAttribute(k_fps, cudaFuncAttributeMaxDynamicSharedMemorySize, SM3);
    cudaFuncSetAttribute(k_view, cudaFuncAttributeMaxDynamicSharedMemorySize, SM4);

    k_prep<<<256, 256>>>(w1, c1w);
    dim3 g1((Np + TPTS - 1) / TPTS, Bb);
    k_gemm_mask<<<g1, 256, SM1>>>(F, b1, gg, be, mm, vv, w2, b2, out);
    k_fps<<<Bb, FT, SM3>>>(xyz, out);
    k_gather<<<Bb * Cc * NS / 256, 256>>>(F, out);
    dim3 g4(NS / TPTS, Bb);
    k_view<<<g4, 256, SM4>>>(c1b, bng, bnb, bnm, bnv, c2w, c2b, out);
}

// round 13
// speedup vs baseline: 1.1857x; 1.1857x over previous
#include <cuda_runtime.h>
#include <cuda_bf16.h>
#include <math.h>
#include <stdint.h>

constexpr int Bb = 4;
constexpr int Np = 20000;
constexpr int Cc = 256;
constexpr int NS = 1024;
constexpr int NV = 300;

// output offsets (float32 elements), reference return order, row-major flatten
constexpr size_t OFF0 = 0;        // objectness (B,2,N)
constexpr size_t OFF1 = 160000;   // graspness (B,N)
constexpr size_t OFF2 = 240000;   // graspable_xyz (B,NS,3)
constexpr size_t OFF3 = 252288;   // graspable_inds (B,NS)
constexpr size_t OFF4 = 256384;   // graspable_features (B,C,NS)
constexpr size_t OFF5 = 1304960;  // fp2_graspness (B,NS)
constexpr size_t OFF6 = 1309056;  // vp_xyz (B,NS,3)
constexpr size_t OFF7 = 1321344;  // top_view_inds (B,NS)
constexpr size_t OFF8 = 1325440;  // vp_rot (B,NS,3,3)

__device__ unsigned char g_mask[Bb * Np];
__device__ int    g_cidx[Bb][Np];
__device__ float4 g_cxyz[Bb][Np];
__device__ int    g_sel[Bb][NS];
__device__ unsigned long long g_W1t[Cc * Cc];
__device__ unsigned long long g_c1wt[Cc * Cc];

// ---------- f32x2 helpers (per-lane bit-identical to scalar __f*_rn) ----------
__device__ __forceinline__ unsigned long long pk2(float a, float b) {
    unsigned long long r;
    asm("mov.b64 %0, {%1, %2};" : "=l"(r) : "f"(a), "f"(b));
    return r;
}
__device__ __forceinline__ void up2(unsigned long long v, float& a, float& b) {
    asm("mov.b64 {%0, %1}, %2;" : "=f"(a), "=f"(b) : "l"(v));
}
__device__ __forceinline__ unsigned long long fma2(unsigned long long a, unsigned long long b,
                                                   unsigned long long c) {
    unsigned long long d;
    asm("fma.rn.f32x2 %0, %1, %2, %3;" : "=l"(d) : "l"(a), "l"(b), "l"(c));
    return d;
}
__device__ __forceinline__ unsigned long long add2(unsigned long long a, unsigned long long b) {
    unsigned long long d;
    asm("add.rn.f32x2 %0, %1, %2;" : "=l"(d) : "l"(a), "l"(b));
    return d;
}
__device__ __forceinline__ unsigned long long mul2(unsigned long long a, unsigned long long b) {
    unsigned long long d;
    asm("mul.rn.f32x2 %0, %1, %2;" : "=l"(d) : "l"(a), "l"(b));
    return d;
}
__device__ __forceinline__ void cpa16(unsigned s, const void* g) {
    asm volatile("cp.async.cg.shared.global [%0], [%1], 16;" :: "r"(s), "l"(g) : "memory");
}

// ================= prepass: transpose + duplicate weights =================
__global__ void k_prep(const float* __restrict__ W1, const float* __restrict__ c1w) {
    int i = blockIdx.x * 256 + threadIdx.x;
    int co = i >> 8, ci = i & 255;
    float w = W1[i];
    g_W1t[ci * 256 + co] = pk2(w, w);
    float v = c1w[i];
    g_c1wt[ci * 256 + co] = pk2(v, v);
}

// ================= wide gather: graspable_features =================
__global__ __launch_bounds__(256) void k_gather(const float* __restrict__ F,
                                                float* __restrict__ out) {
    int i = blockIdx.x * 256 + threadIdx.x;
    int s = i & (NS - 1);
    int c = (i >> 10) & 255;
    int b = i >> 18;
    int idx = g_sel[b][s];
    out[OFF4 + (size_t)b * Cc * NS + (size_t)c * NS + s] =
        F[(size_t)b * Cc * Np + (size_t)c * Np + idx];
}

// ---------- GEMM tile constants (64 points x 256 co per block) ----------
constexpr int TPTS = 64;
constexpr int SM_FSM  = 0;       // 16384 floats
constexpr int SM_WBUF = 16384;   // 2 bufs x 2048 u64
constexpr int SM_W2   = 24576;   // 768
constexpr int SM_B2   = 25344;   // 4
constexpr int SM1_FLOATS = 25348;
constexpr int SM_VSM = 25348;    // 900
constexpr int SM_VPS = 26248;    // 192
constexpr int SM4_FLOATS = 26440;

__device__ __forceinline__ void gemm_tile(const unsigned long long* __restrict__ Wt,
                                          float* sm, int tid, int tx, int ty,
                                          float acc[8][8]) {
    float* fsm = sm + SM_FSM;
    unsigned long long* wsmU = reinterpret_cast<unsigned long long*>(sm + SM_WBUF);
    unsigned wbase = (unsigned)__cvta_generic_to_shared(wsmU);

    unsigned long long acc2[8][4];
#pragma unroll
    for (int j = 0; j < 8; ++j)
#pragma unroll
        for (int q = 0; q < 4; ++q) acc2[j][q] = 0ull;

    {
        const char* src = (const char*)Wt;
#pragma unroll
        for (int r = 0; r < 4; ++r)
            cpa16(wbase + (r * 256 + tid) * 16, src + (r * 256 + tid) * 16);
        asm volatile("cp.async.commit_group;" ::: "memory");
    }

    for (int ck = 0; ck < 32; ++ck) {
        asm volatile("cp.async.wait_group 0;" ::: "memory");
        __syncthreads();
        if (ck < 31) {
            const char* src = (const char*)(Wt + (ck + 1) * 2048);
            unsigned d = wbase + ((ck + 1) & 1) * 16384;
#pragma unroll
            for (int r = 0; r < 4; ++r)
                cpa16(d + (r * 256 + tid) * 16, src + (r * 256 + tid) * 16);
            asm volatile("cp.async.commit_group;" ::: "memory");
        }
        const unsigned long long* wbuf = wsmU + (ck & 1) * 2048;
#pragma unroll
        for (int ci = 0; ci < 8; ++ci) {
            const ulonglong2* wp =
                reinterpret_cast<const ulonglong2*>(wbuf + ci * 256 + 8 * ty);
            ulonglong2 w0 = wp[0], w1 = wp[1], w2 = wp[2], w3 = wp[3];
            const ulonglong2* fq = reinterpret_cast<const ulonglong2*>(
                fsm + (ck * 8 + ci) * TPTS + 8 * tx);
            ulonglong2 q0 = fq[0], q1 = fq[1];
            unsigned long long f2[4] = {q0.x, q0.y, q1.x, q1.y};
            unsigned long long wd[8] = {w0.x, w0.y, w1.x, w1.y, w2.x, w2.y, w3.x, w3.y};
#pragma unroll
            for (int j = 0; j < 8; ++j)
#pragma unroll
                for (int q = 0; q < 4; ++q) acc2[j][q] = fma2(f2[q], wd[j], acc2[j][q]);
        }
    }
    __syncthreads();
#pragma unroll
    for (int j = 0; j < 8; ++j)
#pragma unroll
        for (int q = 0; q < 4; ++q) up2(acc2[j][q], acc[j][2 * q], acc[j][2 * q + 1]);
}

__device__ __forceinline__ void bn_params(const float* gg, const float* be, const float* mm,
                                          const float* vv, const float* b1, int ty,
                                          float sc[8], float bias2[8], float b1v[8]) {
#pragma unroll
    for (int j = 0; j < 8; ++j) {
        int co = 8 * ty + j;
        float s = __fdiv_rn(gg[co], sqrtf(__fadd_rn(vv[co], 1e-5f)));
        sc[j] = s;
        bias2[j] = __fsub_rn(be[co], __fmul_rn(mm[co], s));
        b1v[j] = b1[co];
    }
}

__device__ __forceinline__ void head3(const float* w2sm, float acc[8][8],
                                      const float sc[8], const float bias2[8],
                                      const float b1v[8], int ty, float p3[3][8]) {
#pragma unroll
    for (int j = 0; j < 8; ++j) {
        int co = 8 * ty + j;
        float w0 = w2sm[co], w1c = w2sm[256 + co], w2c = w2sm[512 + co];
#pragma unroll
        for (int p = 0; p < 8; ++p) {
            float t = __fadd_rn(acc[j][p], b1v[j]);
            t = __fmul_rn(t, sc[j]);
            t = __fadd_rn(t, bias2[j]);
            float h = fmaxf(t, 0.f);
            p3[0][p] = fmaf(w0, h, p3[0][p]);
            p3[1][p] = fmaf(w1c, h, p3[1][p]);
            p3[2][p] = fmaf(w2c, h, p3[2][p]);
        }
    }
}

__device__ __forceinline__ void reduce3(float* red, float p3[3][8], int tx, int ty) {
#pragma unroll
    for (int k = 0; k < 3; ++k)
#pragma unroll
        for (int p = 0; p < 8; ++p) red[ty * 192 + k * 64 + 8 * tx + p] = p3[k][p];
    __syncthreads();
    for (int s = 16; s >= 1; s >>= 1) {
        if (ty < s) {
#pragma unroll
            for (int k = 0; k < 3; ++k)
#pragma unroll
                for (int p = 0; p < 8; ++p)
                    red[ty * 192 + k * 64 + 8 * tx + p] +=
                        red[(ty + s) * 192 + k * 64 + 8 * tx + p];
        }
        __syncthreads();
    }
}

// ================= K1 =================
__global__ __launch_bounds__(256, 2) void k_gemm_mask(
    const float* __restrict__ F, const float* __restrict__ b1,
    const float* __restrict__ gg, const float* __restrict__ be, const float* __restrict__ mm,
    const float* __restrict__ vv, const float* __restrict__ W2, const float* __restrict__ b2,
    float* __restrict__ out) {
    extern __shared__ float sm[];
    float* fsm  = sm + SM_FSM;
    float* w2sm = sm + SM_W2;
    float* b2sm = sm + SM_B2;

    int b = blockIdx.y, n0 = blockIdx.x * TPTS, tid = threadIdx.x;
    int tx = tid & 7, ty = tid >> 3;

    for (int t = tid; t < 768; t += 256) w2sm[t] = W2[t];
    if (tid < 3) b2sm[tid] = b2[tid];

    const float* Fb = F + (size_t)b * Cc * Np;
    for (int idx = tid; idx < 256 * TPTS; idx += 256) {
        int c = idx >> 6, p = idx & 63;
        int n = n0 + p;
        fsm[idx] = (n < Np) ? Fb[(size_t)c * Np + n] : 0.f;
    }
    __syncthreads();

    float acc[8][8];
    gemm_tile(g_W1t, sm, tid, tx, ty, acc);

    float sc[8], bias2[8], b1v[8];
    bn_params(gg, be, mm, vv, b1, ty, sc, bias2, b1v);

    float p3[3][8];
#pragma unroll
    for (int k = 0; k < 3; ++k)
#pragma unroll
        for (int p = 0; p < 8; ++p) p3[k][p] = 0.f;
    head3(w2sm, acc, sc, bias2, b1v, ty, p3);

    float* red = fsm;
    reduce3(red, p3, tx, ty);

    if (ty == 0) {
#pragma unroll
        for (int p = 0; p < 8; ++p) {
            int pt = 8 * tx + p;
            int n = n0 + pt;
            if (n < Np) {
                float s0 = __fadd_rn(red[pt], b2sm[0]);
                float s1 = __fadd_rn(red[64 + pt], b2sm[1]);
                float gr = __fadd_rn(red[128 + pt], b2sm[2]);
                out[OFF0 + (size_t)b * 2 * Np + n] = s0;
                out[OFF0 + (size_t)b * 2 * Np + Np + n] = s1;
                out[OFF1 + (size_t)b * Np + n] = gr;
                g_mask[b * Np + n] = (unsigned char)((s1 > s0) && (gr > 0.1f));
            }
        }
    }
}

// ================= K3: 512-thread packed FPS (round-11 proven config) ==========
constexpr int FT    = 512;       // threads
constexpr int RPAIR = 5;         // 5 pairs -> 10 reg slots = 5120 pts
constexpr int RREG  = 5120;
constexpr int SMPTS = 9216;      // xyz slots in smem (18 slots)
constexpr int NDSM  = Np - RREG; // 14880 smem dists for idx >= RREG
// smem byte offsets
constexpr int FP_SXYZ  = 0;          // 147456
constexpr int FP_DIST  = 147456;     // 59520
constexpr int FP_SEQ   = 206976;     // 4096
constexpr int FP_REDD  = 211072;     // 128
constexpr int FP_REDI  = 211200;     // 128
constexpr int FP_WCNT  = 211328;     // 64
constexpr int FP_SBASE = 211392;     // 64
constexpr int FP_BYTES = 211456;

__global__ __launch_bounds__(FT, 1) void k_fps(const float* __restrict__ xyz,
                                               float* __restrict__ out) {
    extern __shared__ char smc[];
    float4*   sxyz  = (float4*)(smc + FP_SXYZ);
    float*    distSm= (float*)(smc + FP_DIST);
    int*      seq   = (int*)(smc + FP_SEQ);
    unsigned* redD  = (unsigned*)(smc + FP_REDD);
    int*      redI  = (int*)(smc + FP_REDI);
    int*      wcnt  = (int*)(smc + FP_WCNT);
    int*      sBase = (int*)(smc + FP_SBASE);

    int b = blockIdx.x, tid = threadIdx.x, lane = tid & 31, wid = tid >> 5;
    const float* xb = xyz + (size_t)b * Np * 3;

    if (tid == 0) sBase[0] = 0;
    __syncthreads();

    // stable stream compaction of masked points
    for (int c0 = 0; c0 < Np; c0 += FT) {
        int n = c0 + tid;
        bool mk = (n < Np) && g_mask[b * Np + n];
        unsigned bal = __ballot_sync(0xffffffffu, mk);
        int pre = __popc(bal & ((1u << lane) - 1u));
        if (lane == 0) wcnt[wid] = __popc(bal);
        __syncthreads();
        if (tid == 0) {
            int a = sBase[0];
            for (int w = 0; w < FT / 32; ++w) { int t = wcnt[w]; wcnt[w] = a; a += t; }
            sBase[0] = a;
        }
        __syncthreads();
        if (mk) {
            int pos = wcnt[wid] + pre;
            float4 p = make_float4(xb[n * 3], xb[n * 3 + 1], xb[n * 3 + 2], 0.f);
            g_cidx[b][pos] = n;
            g_cxyz[b][pos] = p;
            if (pos < SMPTS) sxyz[pos] = p;
        }
        __syncthreads();
    }
    int M = sBase[0];
    const float NEGINF = __int_as_float(0xff800000);

    float rd[2 * RPAIR];
#pragma unroll
    for (int k = 0; k < 2 * RPAIR; ++k)
        rd[k] = (k * FT + tid < M) ? 1e10f : NEGINF;
    unsigned long long rxp[RPAIR], ryp[RPAIR], rzp[RPAIR];
#pragma unroll
    for (int m = 0; m < RPAIR; ++m) {  // stale reads beyond M guarded by rd=NEGINF
        float4 p0 = sxyz[(2 * m) * FT + tid];
        float4 p1 = sxyz[(2 * m + 1) * FT + tid];
        rxp[m] = pk2(p0.x, p1.x);
        ryp[m] = pk2(p0.y, p1.y);
        rzp[m] = pk2(p0.z, p1.z);
    }
    for (int it = tid; it < NDSM; it += FT)
        distSm[it] = (RREG + it < M) ? 1e10f : NEGINF;
    if (tid == 0) seq[0] = 0;
    __syncthreads();

    int kmax = (M + FT - 1) / FT;
    if (kmax > SMPTS / FT) kmax = SMPTS / FT;

    if (M > 0) {
        float4 p0 = sxyz[0];
        float px = p0.x, py = p0.y, pz = p0.z;
        for (int s = 1; s < NS; ++s) {
            unsigned long long ncx = pk2(-px, -px);
            unsigned long long ncy = pk2(-py, -py);
            unsigned long long ncz = pk2(-pz, -pz);
            float best = NEGINF;
            int bi = 0x7fffffff;
#pragma unroll
            for (int m = 0; m < RPAIR; ++m) {
                if (2 * m * FT < M) {  // uniform branch
                    unsigned long long dx2 = add2(rxp[m], ncx);
                    unsigned long long dy2 = add2(ryp[m], ncy);
                    unsigned long long dz2 = add2(rzp[m], ncz);
                    unsigned long long d2 = add2(
                        add2(mul2(dx2, dx2), mul2(dy2, dy2)), mul2(dz2, dz2));
                    float da, db;
                    up2(d2, da, db);
                    float nda = fminf(rd[2 * m], da);
                    rd[2 * m] = nda;
                    if (nda > best) { best = nda; bi = (2 * m) * FT + tid; }
                    float ndb = fminf(rd[2 * m + 1], db);
                    rd[2 * m + 1] = ndb;
                    if (ndb > best) { best = ndb; bi = (2 * m + 1) * FT + tid; }
                }
            }
            for (int k = 2 * RPAIR; k < kmax; ++k) {  // smem slots (rare)
                int i = k * FT + tid;
                float4 p = sxyz[i];
                float dx = __fsub_rn(p.x, px);
                float dy = __fsub_rn(p.y, py);
                float dz = __fsub_rn(p.z, pz);
                float d = __fadd_rn(__fadd_rn(__fmul_rn(dx, dx), __fmul_rn(dy, dy)),
                                    __fmul_rn(dz, dz));
                float nd = fminf(distSm[i - RREG], d);
                distSm[i - RREG] = nd;
                if (nd > best) { best = nd; bi = i; }
            }
            for (int i = SMPTS + tid; i < M; i += FT) {  // global overflow (rarer)
                float4 p = g_cxyz[b][i];
                float dx = __fsub_rn(p.x, px);
                float dy = __fsub_rn(p.y, py);
                float dz = __fsub_rn(p.z, pz);
                float d = __fadd_rn(__fadd_rn(__fmul_rn(dx, dx), __fmul_rn(dy, dy)),
                                    __fmul_rn(dz, dz));
                float nd = fminf(distSm[i - RREG], d);
                distSm[i - RREG] = nd;
                if (nd > best) { best = nd; bi = i; }
            }
            unsigned db = (bi == 0x7fffffff) ? 0u : __float_as_uint(best);
            unsigned mx = __reduce_max_sync(0xffffffffu, db);
            int cand = (db == mx) ? bi : 0x7fffffff;
            int wmin = __reduce_min_sync(0xffffffffu, cand);
            int buf = (s & 1) * 16;
            if (lane == 0) { redD[buf + wid] = mx; redI[buf + wid] = wmin; }
            __syncthreads();
            unsigned db2 = redD[buf + (lane & 15)];
            int bi2 = redI[buf + (lane & 15)];
            unsigned mx2 = __reduce_max_sync(0xffffffffu, db2);
            int cand2 = (db2 == mx2) ? bi2 : 0x7fffffff;
            int win = __reduce_min_sync(0xffffffffu, cand2);
            if (tid == 0) seq[s] = win;
            float4 pw = (win < SMPTS) ? sxyz[win] : g_cxyz[b][win];
            px = pw.x; py = pw.y; pz = pw.z;
        }
    }
    __syncthreads();

    // epilogue: inds / xyz / fp2_graspness
    for (int t = tid; t < NS; t += FT) {
        int orig; float x, y, z;
        if (M > 0) {
            int c = seq[t];
            orig = g_cidx[b][c];
            float4 p = g_cxyz[b][c];
            x = p.x; y = p.y; z = p.z;
        } else {
            orig = 0; x = xb[0]; y = xb[1]; z = xb[2];
        }
        out[OFF3 + (size_t)b * NS + t] = (float)orig;
        out[OFF2 + (size_t)b * NS * 3 + t * 3 + 0] = x;
        out[OFF2 + (size_t)b * NS * 3 + t * 3 + 1] = y;
        out[OFF2 + (size_t)b * NS * 3 + t * 3 + 2] = z;
        out[OFF5 + (size_t)b * NS + t] = out[OFF1 + (size_t)b * Np + orig];
        g_sel[b][t] = orig;
    }
}

// ================= K4 (reads gathered features coalesced from out[OFF4]) ========
__global__ __launch_bounds__(256, 2) void k_view(
    const float* __restrict__ b1,
    const float* __restrict__ gg, const float* __restrict__ be, const float* __restrict__ mm,
    const float* __restrict__ vv, const float* __restrict__ W2, const float* __restrict__ b2,
    float* __restrict__ out) {
    extern __shared__ float sm[];
    float* fsm  = sm + SM_FSM;
    float* w2sm = sm + SM_W2;
    float* b2sm = sm + SM_B2;
    float* vsm  = sm + SM_VSM;
    float* vps  = sm + SM_VPS;

    int b = blockIdx.y, s0 = blockIdx.x * TPTS, tid = threadIdx.x;
    int tx = tid & 7, ty = tid >> 3;

    for (int t = tid; t < 768; t += 256) w2sm[t] = W2[t];
    if (tid < 3) b2sm[tid] = b2[tid];

    for (int i = tid; i < NV; i += 256) {
        double z = (2.0 * (double)i + 1.0) / (double)NV - 1.0;
        double r = sqrt(fmax(1.0 - z * z, 0.0));
        double phi = (sqrt(5.0) - 1.0) / 2.0;
        double ang = (2.0 * 3.14159265358979323846) * (double)i * phi;
        float x = (float)(r * cos(ang)), y = (float)(r * sin(ang)), zf = (float)z;
        float nr2 = __fadd_rn(__fadd_rn(__fmul_rn(x, x), __fmul_rn(y, y)), __fmul_rn(zf, zf));
        float nr = fmaxf(sqrtf(nr2), 1e-8f);
        vsm[i * 3 + 0] = __fdiv_rn(x, nr);
        vsm[i * 3 + 1] = __fdiv_rn(y, nr);
        vsm[i * 3 + 2] = __fdiv_rn(zf, nr);
    }

    const float* Gb = out + OFF4 + (size_t)b * Cc * NS;
    for (int idx = tid; idx < 256 * 16; idx += 256) {
        int c = idx >> 4, q = idx & 15;
        reinterpret_cast<float4*>(fsm + c * 64)[q] =
            *reinterpret_cast<const float4*>(Gb + (size_t)c * NS + s0 + 4 * q);
    }
    __syncthreads();

    float acc[8][8];
    gemm_tile(g_c1wt, sm, tid, tx, ty, acc);

    float sc[8], bias2[8], b1v[8];
    bn_params(gg, be, mm, vv, b1, ty, sc, bias2, b1v);

    float p3[3][8];
#pragma unroll
    for (int k = 0; k < 3; ++k)
#pragma unroll
        for (int p = 0; p < 8; ++p) p3[k][p] = 0.f;
    head3(w2sm, acc, sc, bias2, b1v, ty, p3);

    float* red = fsm;
    reduce3(red, p3, tx, ty);

    if (ty == 0) {
#pragma unroll
        for (int p = 0; p < 8; ++p) {
            int pt = 8 * tx + p;
            int s = s0 + pt;
            float v0 = __fadd_rn(red[pt], b2sm[0]);
            float v1 = __fadd_rn(red[64 + pt], b2sm[1]);
            float v2 = __fadd_rn(red[128 + pt], b2sm[2]);
            out[OFF6 + (size_t)b * NS * 3 + (size_t)s * 3 + 0] = v0;
            out[OFF6 + (size_t)b * NS * 3 + (size_t)s * 3 + 1] = v1;
            out[OFF6 + (size_t)b * NS * 3 + (size_t)s * 3 + 2] = v2;
            vps[pt * 3 + 0] = v0; vps[pt * 3 + 1] = v1; vps[pt * 3 + 2] = v2;
        }
    }
    __syncthreads();

    if (tid < TPTS) {
        int s = s0 + tid;
        float vx = vps[tid * 3], vy = vps[tid * 3 + 1], vz = vps[tid * 3 + 2];
        float n2 = __fadd_rn(__fadd_rn(__fmul_rn(vx, vx), __fmul_rn(vy, vy)), __fmul_rn(vz, vz));
        float nr = fmaxf(sqrtf(n2), 1e-8f);
        float ax_ = __fdiv_rn(vx, nr), ay_ = __fdiv_rn(vy, nr), az_ = __fdiv_rn(vz, nr);
        float best = __int_as_float(0xff800000);
        int bi = 0;
        for (int v = 0; v < NV; ++v) {
            float c = __fadd_rn(__fadd_rn(__fmul_rn(ax_, vsm[v * 3]),
                                          __fmul_rn(ay_, vsm[v * 3 + 1])),
                                __fmul_rn(az_, vsm[v * 3 + 2]));
            if (c > best) { best = c; bi = v; }
        }
        out[OFF7 + (size_t)b * NS + s] = (float)bi;

        float tx0 = -vx, tx1 = -vy, tx2 = -vz;
        float ay0 = -tx1, ay1 = tx0, ay2 = 0.f;
        float s2 = ay0 * ay0 + ay1 * ay1;
        if (s2 == 0.f) { ay0 = 0.f; ay1 = 1.f; ay2 = 0.f; }
        float an = sqrtf(tx0 * tx0 + tx1 * tx1 + tx2 * tx2);
        float nx0 = tx0 / an, nx1 = tx1 / an, nx2 = tx2 / an;
        float bn = sqrtf(ay0 * ay0 + ay1 * ay1 + ay2 * ay2);
        float ny0 = ay0 / bn, ny1 = ay1 / bn, ny2 = ay2 / bn;
        float nz0 = nx1 * ny2 - nx2 * ny1;
        float nz1 = nx2 * ny0 - nx0 * ny2;
        float nz2 = nx0 * ny1 - nx1 * ny0;
        size_t base = OFF8 + ((size_t)b * NS + s) * 9;
        out[base + 0] = nx0; out[base + 1] = ny0; out[base + 2] = nz0;
        out[base + 3] = nx1; out[base + 4] = ny1; out[base + 5] = nz1;
        out[base + 6] = nx2; out[base + 7] = ny2; out[base + 8] = nz2;
    }
}

// ================= launch (robust input-order detection) =================
extern "C" void kernel_launch(void* const* d_in, const int* in_sizes, int n_in,
                              void* d_out, int out_size) {
    const float *xyz, *F, *w1, *b1, *gg, *be, *mm, *vv, *w2, *b2;
    const float *c1w, *c1b, *bng, *bnb, *bnm, *bnv, *c2w, *c2b;

    int imax = 0;
    for (int i = 1; i < n_in; ++i)
        if (in_sizes[i] > in_sizes[imax]) imax = i;

    if (imax == 1) {  // dict-insertion / signature order
        xyz = (const float*)d_in[0];  F   = (const float*)d_in[1];
        w1  = (const float*)d_in[2];  b1  = (const float*)d_in[3];
        gg  = (const float*)d_in[4];  be  = (const float*)d_in[5];
        mm  = (const float*)d_in[6];  vv  = (const float*)d_in[7];
        w2  = (const float*)d_in[8];  b2  = (const float*)d_in[9];
        c1w = (const float*)d_in[10]; c1b = (const float*)d_in[11];
        bng = (const float*)d_in[12]; bnb = (const float*)d_in[13];
        bnm = (const float*)d_in[14]; bnv = (const float*)d_in[15];
        c2w = (const float*)d_in[16]; c2b = (const float*)d_in[17];
    } else {          // alphabetical order
        bnb = (const float*)d_in[0];  bng = (const float*)d_in[1];
        bnm = (const float*)d_in[2];  bnv = (const float*)d_in[3];
        c1b = (const float*)d_in[4];  c1w = (const float*)d_in[5];
        c2b = (const float*)d_in[6];  c2w = (const float*)d_in[7];
        b1  = (const float*)d_in[8];  b2  = (const float*)d_in[9];
        be  = (const float*)d_in[10]; gg  = (const float*)d_in[11];
        mm  = (const float*)d_in[12]; vv  = (const float*)d_in[13];
        w1  = (const float*)d_in[14]; w2  = (const float*)d_in[15];
        F   = (const float*)d_in[16]; xyz = (const float*)d_in[17];
    }
    float* out = (float*)d_out;

    const int SM1 = SM1_FLOATS * 4;
    const int SM3 = FP_BYTES;
    const int SM4 = SM4_FLOATS * 4;
    cudaFuncSetAttribute(k_gemm_mask, cudaFuncAttributeMaxDynamicSharedMemorySize, SM1);
    cudaFuncSetAttribute(k_fps, cudaFuncAttributeMaxDynamicSharedMemorySize, SM3);
    cudaFuncSetAttribute(k_view, cudaFuncAttributeMaxDynamicSharedMemorySize, SM4);

    k_prep<<<256, 256>>>(w1, c1w);
    dim3 g1((Np + TPTS - 1) / TPTS, Bb);
    k_gemm_mask<<<g1, 256, SM1>>>(F, b1, gg, be, mm, vv, w2, b2, out);
    k_fps<<<Bb, FT, SM3>>>(xyz, out);
    k_gather<<<Bb * Cc * NS / 256, 256>>>(F, out);
    dim3 g4(NS / TPTS, Bb);
    k_view<<<g4, 256, SM4>>>(c1b, bng, bnb, bnm, bnv, c2w, c2b, out);
}

// round 14
// speedup vs baseline: 1.2251x; 1.0332x over previous
#include <cuda_runtime.h>
#include <cuda_bf16.h>
#include <math.h>
#include <stdint.h>

constexpr int Bb = 4;
constexpr int Np = 20000;
constexpr int Cc = 256;
constexpr int NS = 1024;
constexpr int NV = 300;

// output offsets (float32 elements), reference return order, row-major flatten
constexpr size_t OFF0 = 0;        // objectness (B,2,N)
constexpr size_t OFF1 = 160000;   // graspness (B,N)
constexpr size_t OFF2 = 240000;   // graspable_xyz (B,NS,3)
constexpr size_t OFF3 = 252288;   // graspable_inds (B,NS)
constexpr size_t OFF4 = 256384;   // graspable_features (B,C,NS)
constexpr size_t OFF5 = 1304960;  // fp2_graspness (B,NS)
constexpr size_t OFF6 = 1309056;  // vp_xyz (B,NS,3)
constexpr size_t OFF7 = 1321344;  // top_view_inds (B,NS)
constexpr size_t OFF8 = 1325440;  // vp_rot (B,NS,3,3)

__device__ unsigned char g_mask[Bb * Np];
__device__ int    g_cidx[Bb][Np];
__device__ float4 g_cxyz[Bb][Np];
__device__ int    g_sel[Bb][NS];
__device__ unsigned long long g_W1t[Cc * Cc];
__device__ unsigned long long g_c1wt[Cc * Cc];

// ---------- f32x2 helpers (per-lane bit-identical to scalar __f*_rn) ----------
__device__ __forceinline__ unsigned long long pk2(float a, float b) {
    unsigned long long r;
    asm("mov.b64 %0, {%1, %2};" : "=l"(r) : "f"(a), "f"(b));
    return r;
}
__device__ __forceinline__ void up2(unsigned long long v, float& a, float& b) {
    asm("mov.b64 {%0, %1}, %2;" : "=f"(a), "=f"(b) : "l"(v));
}
__device__ __forceinline__ unsigned long long fma2(unsigned long long a, unsigned long long b,
                                                   unsigned long long c) {
    unsigned long long d;
    asm("fma.rn.f32x2 %0, %1, %2, %3;" : "=l"(d) : "l"(a), "l"(b), "l"(c));
    return d;
}
__device__ __forceinline__ unsigned long long add2(unsigned long long a, unsigned long long b) {
    unsigned long long d;
    asm("add.rn.f32x2 %0, %1, %2;" : "=l"(d) : "l"(a), "l"(b));
    return d;
}
__device__ __forceinline__ unsigned long long mul2(unsigned long long a, unsigned long long b) {
    unsigned long long d;
    asm("mul.rn.f32x2 %0, %1, %2;" : "=l"(d) : "l"(a), "l"(b));
    return d;
}
__device__ __forceinline__ void cpa16(unsigned s, const void* g) {
    asm volatile("cp.async.cg.shared.global [%0], [%1], 16;" :: "r"(s), "l"(g) : "memory");
}

// ================= prepass: transpose + duplicate weights =================
__global__ void k_prep(const float* __restrict__ W1, const float* __restrict__ c1w) {
    int i = blockIdx.x * 256 + threadIdx.x;
    int co = i >> 8, ci = i & 255;
    float w = W1[i];
    g_W1t[ci * 256 + co] = pk2(w, w);
    float v = c1w[i];
    g_c1wt[ci * 256 + co] = pk2(v, v);
}

// ================= wide gather: graspable_features =================
__global__ __launch_bounds__(256) void k_gather(const float* __restrict__ F,
                                                float* __restrict__ out) {
    int i = blockIdx.x * 256 + threadIdx.x;
    int s = i & (NS - 1);
    int c = (i >> 10) & 255;
    int b = i >> 18;
    int idx = g_sel[b][s];
    out[OFF4 + (size_t)b * Cc * NS + (size_t)c * NS + s] =
        F[(size_t)b * Cc * Np + (size_t)c * Np + idx];
}

// ---------- GEMM tile constants (32 points x 256 co per block; 3 CTAs/SM) ------
constexpr int TPTS = 32;
constexpr int SM_FSM  = 0;       // 8192 floats (256 ci x 32 pts) = 32KB
constexpr int SM_WBUF = 8192;    // 2 bufs x 2048 u64 = 8192 floats = 32KB
constexpr int SM_W2   = 16384;   // 768
constexpr int SM_B2   = 17152;   // 4
constexpr int SM1_FLOATS = 17156;
constexpr int SM_VSM = 17156;    // 900
constexpr int SM_VPS = 18056;    // 96 (32 x 3)
constexpr int SM4_FLOATS = 18152;

// tx=tid&7 owns pts 4tx..4tx+3, ty=tid>>3 owns co 8ty..8ty+7.
// Wt: transposed duplicated weights [ci][co] as (w,w) u64. cp.async double-buffered.
__device__ __forceinline__ void gemm_tile(const unsigned long long* __restrict__ Wt,
                                          float* sm, int tid, int tx, int ty,
                                          float acc[8][4]) {
    float* fsm = sm + SM_FSM;
    unsigned long long* wsmU = reinterpret_cast<unsigned long long*>(sm + SM_WBUF);
    unsigned wbase = (unsigned)__cvta_generic_to_shared(wsmU);

    unsigned long long acc2[8][2];
#pragma unroll
    for (int j = 0; j < 8; ++j) { acc2[j][0] = 0ull; acc2[j][1] = 0ull; }

    {   // prologue: issue ck=0 into buf 0 (16KB = 1024 x 16B; 256 thr x 4)
        const char* src = (const char*)Wt;
#pragma unroll
        for (int r = 0; r < 4; ++r)
            cpa16(wbase + (r * 256 + tid) * 16, src + (r * 256 + tid) * 16);
        asm volatile("cp.async.commit_group;" ::: "memory");
    }

    for (int ck = 0; ck < 32; ++ck) {
        asm volatile("cp.async.wait_group 0;" ::: "memory");
        __syncthreads();
        if (ck < 31) {
            const char* src = (const char*)(Wt + (ck + 1) * 2048);
            unsigned d = wbase + ((ck + 1) & 1) * 16384;
#pragma unroll
            for (int r = 0; r < 4; ++r)
                cpa16(d + (r * 256 + tid) * 16, src + (r * 256 + tid) * 16);
            asm volatile("cp.async.commit_group;" ::: "memory");
        }
        const unsigned long long* wbuf = wsmU + (ck & 1) * 2048;
#pragma unroll
        for (int ci = 0; ci < 8; ++ci) {
            const ulonglong2* wp =
                reinterpret_cast<const ulonglong2*>(wbuf + ci * 256 + 8 * ty);
            ulonglong2 w0 = wp[0], w1 = wp[1], w2 = wp[2], w3 = wp[3];
            ulonglong2 q0 = *reinterpret_cast<const ulonglong2*>(
                fsm + (ck * 8 + ci) * TPTS + 4 * tx);
            unsigned long long f2[2] = {q0.x, q0.y};
            unsigned long long wd[8] = {w0.x, w0.y, w1.x, w1.y, w2.x, w2.y, w3.x, w3.y};
#pragma unroll
            for (int j = 0; j < 8; ++j) {
                acc2[j][0] = fma2(f2[0], wd[j], acc2[j][0]);
                acc2[j][1] = fma2(f2[1], wd[j], acc2[j][1]);
            }
        }
    }
    __syncthreads();
#pragma unroll
    for (int j = 0; j < 8; ++j) {
        up2(acc2[j][0], acc[j][0], acc[j][1]);
        up2(acc2[j][1], acc[j][2], acc[j][3]);
    }
}

__device__ __forceinline__ void bn_params(const float* gg, const float* be, const float* mm,
                                          const float* vv, const float* b1, int ty,
                                          float sc[8], float bias2[8], float b1v[8]) {
#pragma unroll
    for (int j = 0; j < 8; ++j) {
        int co = 8 * ty + j;
        float s = __fdiv_rn(gg[co], sqrtf(__fadd_rn(vv[co], 1e-5f)));
        sc[j] = s;
        bias2[j] = __fsub_rn(be[co], __fmul_rn(mm[co], s));
        b1v[j] = b1[co];
    }
}

__device__ __forceinline__ void head3(const float* w2sm, float acc[8][4],
                                      const float sc[8], const float bias2[8],
                                      const float b1v[8], int ty, float p3[3][4]) {
#pragma unroll
    for (int j = 0; j < 8; ++j) {
        int co = 8 * ty + j;
        float w0 = w2sm[co], w1c = w2sm[256 + co], w2c = w2sm[512 + co];
#pragma unroll
        for (int p = 0; p < 4; ++p) {
            float t = __fadd_rn(acc[j][p], b1v[j]);
            t = __fmul_rn(t, sc[j]);
            t = __fadd_rn(t, bias2[j]);
            float h = fmaxf(t, 0.f);
            p3[0][p] = fmaf(w0, h, p3[0][p]);
            p3[1][p] = fmaf(w1c, h, p3[1][p]);
            p3[2][p] = fmaf(w2c, h, p3[2][p]);
        }
    }
}

// tree-reduce over 32 ty groups; result red[k*32 + pt] for ty==0
__device__ __forceinline__ void reduce3(float* red, float p3[3][4], int tx, int ty) {
#pragma unroll
    for (int k = 0; k < 3; ++k)
#pragma unroll
        for (int p = 0; p < 4; ++p) red[ty * 96 + k * 32 + 4 * tx + p] = p3[k][p];
    __syncthreads();
    for (int s = 16; s >= 1; s >>= 1) {
        if (ty < s) {
#pragma unroll
            for (int k = 0; k < 3; ++k)
#pragma unroll
                for (int p = 0; p < 4; ++p)
                    red[ty * 96 + k * 32 + 4 * tx + p] +=
                        red[(ty + s) * 96 + k * 32 + 4 * tx + p];
        }
        __syncthreads();
    }
}

// ================= K1 =================
__global__ __launch_bounds__(256, 3) void k_gemm_mask(
    const float* __restrict__ F, const float* __restrict__ b1,
    const float* __restrict__ gg, const float* __restrict__ be, const float* __restrict__ mm,
    const float* __restrict__ vv, const float* __restrict__ W2, const float* __restrict__ b2,
    float* __restrict__ out) {
    extern __shared__ float sm[];
    float* fsm  = sm + SM_FSM;
    float* w2sm = sm + SM_W2;
    float* b2sm = sm + SM_B2;

    int b = blockIdx.y, n0 = blockIdx.x * TPTS, tid = threadIdx.x;
    int tx = tid & 7, ty = tid >> 3;

    for (int t = tid; t < 768; t += 256) w2sm[t] = W2[t];
    if (tid < 3) b2sm[tid] = b2[tid];

    const float* Fb = F + (size_t)b * Cc * Np;
    for (int idx = tid; idx < 256 * TPTS; idx += 256) {
        int c = idx >> 5, p = idx & 31;
        int n = n0 + p;
        fsm[idx] = (n < Np) ? Fb[(size_t)c * Np + n] : 0.f;
    }
    __syncthreads();

    float acc[8][4];
    gemm_tile(g_W1t, sm, tid, tx, ty, acc);

    float sc[8], bias2[8], b1v[8];
    bn_params(gg, be, mm, vv, b1, ty, sc, bias2, b1v);

    float p3[3][4];
#pragma unroll
    for (int k = 0; k < 3; ++k)
#pragma unroll
        for (int p = 0; p < 4; ++p) p3[k][p] = 0.f;
    head3(w2sm, acc, sc, bias2, b1v, ty, p3);

    float* red = fsm;
    reduce3(red, p3, tx, ty);

    if (ty == 0) {
#pragma unroll
        for (int p = 0; p < 4; ++p) {
            int pt = 4 * tx + p;
            int n = n0 + pt;
            if (n < Np) {
                float s0 = __fadd_rn(red[pt], b2sm[0]);
                float s1 = __fadd_rn(red[32 + pt], b2sm[1]);
                float gr = __fadd_rn(red[64 + pt], b2sm[2]);
                out[OFF0 + (size_t)b * 2 * Np + n] = s0;
                out[OFF0 + (size_t)b * 2 * Np + Np + n] = s1;
                out[OFF1 + (size_t)b * Np + n] = gr;
                g_mask[b * Np + n] = (unsigned char)((s1 > s0) && (gr > 0.1f));
            }
        }
    }
}

// ================= K3: 512-thread packed FPS (round-11 proven config) ==========
constexpr int FT    = 512;       // threads
constexpr int RPAIR = 5;         // 5 pairs -> 10 reg slots = 5120 pts
constexpr int RREG  = 5120;
constexpr int SMPTS = 9216;      // xyz slots in smem (18 slots)
constexpr int NDSM  = Np - RREG; // 14880 smem dists for idx >= RREG
// smem byte offsets
constexpr int FP_SXYZ  = 0;          // 147456
constexpr int FP_DIST  = 147456;     // 59520
constexpr int FP_SEQ   = 206976;     // 4096
constexpr int FP_REDD  = 211072;     // 128
constexpr int FP_REDI  = 211200;     // 128
constexpr int FP_WCNT  = 211328;     // 64
constexpr int FP_SBASE = 211392;     // 64
constexpr int FP_BYTES = 211456;

__global__ __launch_bounds__(FT, 1) void k_fps(const float* __restrict__ xyz,
                                               float* __restrict__ out) {
    extern __shared__ char smc[];
    float4*   sxyz  = (float4*)(smc + FP_SXYZ);
    float*    distSm= (float*)(smc + FP_DIST);
    int*      seq   = (int*)(smc + FP_SEQ);
    unsigned* redD  = (unsigned*)(smc + FP_REDD);
    int*      redI  = (int*)(smc + FP_REDI);
    int*      wcnt  = (int*)(smc + FP_WCNT);
    int*      sBase = (int*)(smc + FP_SBASE);

    int b = blockIdx.x, tid = threadIdx.x, lane = tid & 31, wid = tid >> 5;
    const float* xb = xyz + (size_t)b * Np * 3;

    if (tid == 0) sBase[0] = 0;
    __syncthreads();

    for (int c0 = 0; c0 < Np; c0 += FT) {
        int n = c0 + tid;
        bool mk = (n < Np) && g_mask[b * Np + n];
        unsigned bal = __ballot_sync(0xffffffffu, mk);
        int pre = __popc(bal & ((1u << lane) - 1u));
        if (lane == 0) wcnt[wid] = __popc(bal);
        __syncthreads();
        if (tid == 0) {
            int a = sBase[0];
            for (int w = 0; w < FT / 32; ++w) { int t = wcnt[w]; wcnt[w] = a; a += t; }
            sBase[0] = a;
        }
        __syncthreads();
        if (mk) {
            int pos = wcnt[wid] + pre;
            float4 p = make_float4(xb[n * 3], xb[n * 3 + 1], xb[n * 3 + 2], 0.f);
            g_cidx[b][pos] = n;
            g_cxyz[b][pos] = p;
            if (pos < SMPTS) sxyz[pos] = p;
        }
        __syncthreads();
    }
    int M = sBase[0];
    const float NEGINF = __int_as_float(0xff800000);

    float rd[2 * RPAIR];
#pragma unroll
    for (int k = 0; k < 2 * RPAIR; ++k)
        rd[k] = (k * FT + tid < M) ? 1e10f : NEGINF;
    unsigned long long rxp[RPAIR], ryp[RPAIR], rzp[RPAIR];
#pragma unroll
    for (int m = 0; m < RPAIR; ++m) {
        float4 p0 = sxyz[(2 * m) * FT + tid];
        float4 p1 = sxyz[(2 * m + 1) * FT + tid];
        rxp[m] = pk2(p0.x, p1.x);
        ryp[m] = pk2(p0.y, p1.y);
        rzp[m] = pk2(p0.z, p1.z);
    }
    for (int it = tid; it < NDSM; it += FT)
        distSm[it] = (RREG + it < M) ? 1e10f : NEGINF;
    if (tid == 0) seq[0] = 0;
    __syncthreads();

    int kmax = (M + FT - 1) / FT;
    if (kmax > SMPTS / FT) kmax = SMPTS / FT;

    if (M > 0) {
        float4 p0 = sxyz[0];
        float px = p0.x, py = p0.y, pz = p0.z;
        for (int s = 1; s < NS; ++s) {
            unsigned long long ncx = pk2(-px, -px);
            unsigned long long ncy = pk2(-py, -py);
            unsigned long long ncz = pk2(-pz, -pz);
            float best = NEGINF;
            int bi = 0x7fffffff;
#pragma unroll
            for (int m = 0; m < RPAIR; ++m) {
                if (2 * m * FT < M) {
                    unsigned long long dx2 = add2(rxp[m], ncx);
                    unsigned long long dy2 = add2(ryp[m], ncy);
                    unsigned long long dz2 = add2(rzp[m], ncz);
                    unsigned long long d2 = add2(
                        add2(mul2(dx2, dx2), mul2(dy2, dy2)), mul2(dz2, dz2));
                    float da, db;
                    up2(d2, da, db);
                    float nda = fminf(rd[2 * m], da);
                    rd[2 * m] = nda;
                    if (nda > best) { best = nda; bi = (2 * m) * FT + tid; }
                    float ndb = fminf(rd[2 * m + 1], db);
                    rd[2 * m + 1] = ndb;
                    if (ndb > best) { best = ndb; bi = (2 * m + 1) * FT + tid; }
                }
            }
            for (int k = 2 * RPAIR; k < kmax; ++k) {
                int i = k * FT + tid;
                float4 p = sxyz[i];
                float dx = __fsub_rn(p.x, px);
                float dy = __fsub_rn(p.y, py);
                float dz = __fsub_rn(p.z, pz);
                float d = __fadd_rn(__fadd_rn(__fmul_rn(dx, dx), __fmul_rn(dy, dy)),
                                    __fmul_rn(dz, dz));
                float nd = fminf(distSm[i - RREG], d);
                distSm[i - RREG] = nd;
                if (nd > best) { best = nd; bi = i; }
            }
            for (int i = SMPTS + tid; i < M; i += FT) {
                float4 p = g_cxyz[b][i];
                float dx = __fsub_rn(p.x, px);
                float dy = __fsub_rn(p.y, py);
                float dz = __fsub_rn(p.z, pz);
                float d = __fadd_rn(__fadd_rn(__fmul_rn(dx, dx), __fmul_rn(dy, dy)),
                                    __fmul_rn(dz, dz));
                float nd = fminf(distSm[i - RREG], d);
                distSm[i - RREG] = nd;
                if (nd > best) { best = nd; bi = i; }
            }
            unsigned db = (bi == 0x7fffffff) ? 0u : __float_as_uint(best);
            unsigned mx = __reduce_max_sync(0xffffffffu, db);
            int cand = (db == mx) ? bi : 0x7fffffff;
            int wmin = __reduce_min_sync(0xffffffffu, cand);
            int buf = (s & 1) * 16;
            if (lane == 0) { redD[buf + wid] = mx; redI[buf + wid] = wmin; }
            __syncthreads();
            unsigned db2 = redD[buf + (lane & 15)];
            int bi2 = redI[buf + (lane & 15)];
            unsigned mx2 = __reduce_max_sync(0xffffffffu, db2);
            int cand2 = (db2 == mx2) ? bi2 : 0x7fffffff;
            int win = __reduce_min_sync(0xffffffffu, cand2);
            if (tid == 0) seq[s] = win;
            float4 pw = (win < SMPTS) ? sxyz[win] : g_cxyz[b][win];
            px = pw.x; py = pw.y; pz = pw.z;
        }
    }
    __syncthreads();

    for (int t = tid; t < NS; t += FT) {
        int orig; float x, y, z;
        if (M > 0) {
            int c = seq[t];
            orig = g_cidx[b][c];
            float4 p = g_cxyz[b][c];
            x = p.x; y = p.y; z = p.z;
        } else {
            orig = 0; x = xb[0]; y = xb[1]; z = xb[2];
        }
        out[OFF3 + (size_t)b * NS + t] = (float)orig;
        out[OFF2 + (size_t)b * NS * 3 + t * 3 + 0] = x;
        out[OFF2 + (size_t)b * NS * 3 + t * 3 + 1] = y;
        out[OFF2 + (size_t)b * NS * 3 + t * 3 + 2] = z;
        out[OFF5 + (size_t)b * NS + t] = out[OFF1 + (size_t)b * Np + orig];
        g_sel[b][t] = orig;
    }
}

// ================= K4 (reads gathered features coalesced from out[OFF4]) ========
__global__ __launch_bounds__(256, 3) void k_view(
    const float* __restrict__ b1,
    const float* __restrict__ gg, const float* __restrict__ be, const float* __restrict__ mm,
    const float* __restrict__ vv, const float* __restrict__ W2, const float* __restrict__ b2,
    float* __restrict__ out) {
    extern __shared__ float sm[];
    float* fsm  = sm + SM_FSM;
    float* w2sm = sm + SM_W2;
    float* b2sm = sm + SM_B2;
    float* vsm  = sm + SM_VSM;
    float* vps  = sm + SM_VPS;

    int b = blockIdx.y, s0 = blockIdx.x * TPTS, tid = threadIdx.x;
    int tx = tid & 7, ty = tid >> 3;

    for (int t = tid; t < 768; t += 256) w2sm[t] = W2[t];
    if (tid < 3) b2sm[tid] = b2[tid];

    for (int i = tid; i < NV; i += 256) {
        double z = (2.0 * (double)i + 1.0) / (double)NV - 1.0;
        double r = sqrt(fmax(1.0 - z * z, 0.0));
        double phi = (sqrt(5.0) - 1.0) / 2.0;
        double ang = (2.0 * 3.14159265358979323846) * (double)i * phi;
        float x = (float)(r * cos(ang)), y = (float)(r * sin(ang)), zf = (float)z;
        float nr2 = __fadd_rn(__fadd_rn(__fmul_rn(x, x), __fmul_rn(y, y)), __fmul_rn(zf, zf));
        float nr = fmaxf(sqrtf(nr2), 1e-8f);
        vsm[i * 3 + 0] = __fdiv_rn(x, nr);
        vsm[i * 3 + 1] = __fdiv_rn(y, nr);
        vsm[i * 3 + 2] = __fdiv_rn(zf, nr);
    }

    // coalesced float4 tile load: 256 c x 8 float4 (32 samples)
    const float* Gb = out + OFF4 + (size_t)b * Cc * NS;
    for (int idx = tid; idx < 256 * 8; idx += 256) {
        int c = idx >> 3, q = idx & 7;
        reinterpret_cast<float4*>(fsm + c * TPTS)[q] =
            *reinterpret_cast<const float4*>(Gb + (size_t)c * NS + s0 + 4 * q);
    }
    __syncthreads();

    float acc[8][4];
    gemm_tile(g_c1wt, sm, tid, tx, ty, acc);

    float sc[8], bias2[8], b1v[8];
    bn_params(gg, be, mm, vv, b1, ty, sc, bias2, b1v);

    float p3[3][4];
#pragma unroll
    for (int k = 0; k < 3; ++k)
#pragma unroll
        for (int p = 0; p < 4; ++p) p3[k][p] = 0.f;
    head3(w2sm, acc, sc, bias2, b1v, ty, p3);

    float* red = fsm;
    reduce3(red, p3, tx, ty);

    if (ty == 0) {
#pragma unroll
        for (int p = 0; p < 4; ++p) {
            int pt = 4 * tx + p;
            int s = s0 + pt;
            float v0 = __fadd_rn(red[pt], b2sm[0]);
            float v1 = __fadd_rn(red[32 + pt], b2sm[1]);
            float v2 = __fadd_rn(red[64 + pt], b2sm[2]);
            out[OFF6 + (size_t)b * NS * 3 + (size_t)s * 3 + 0] = v0;
            out[OFF6 + (size_t)b * NS * 3 + (size_t)s * 3 + 1] = v1;
            out[OFF6 + (size_t)b * NS * 3 + (size_t)s * 3 + 2] = v2;
            vps[pt * 3 + 0] = v0; vps[pt * 3 + 1] = v1; vps[pt * 3 + 2] = v2;
        }
    }
    __syncthreads();

    if (tid < TPTS) {
        int s = s0 + tid;
        float vx = vps[tid * 3], vy = vps[tid * 3 + 1], vz = vps[tid * 3 + 2];
        float n2 = __fadd_rn(__fadd_rn(__fmul_rn(vx, vx), __fmul_rn(vy, vy)), __fmul_rn(vz, vz));
        float nr = fmaxf(sqrtf(n2), 1e-8f);
        float ax_ = __fdiv_rn(vx, nr), ay_ = __fdiv_rn(vy, nr), az_ = __fdiv_rn(vz, nr);
        float best = __int_as_float(0xff800000);
        int bi = 0;
        for (int v = 0; v < NV; ++v) {
            float c = __fadd_rn(__fadd_rn(__fmul_rn(ax_, vsm[v * 3]),
                                          __fmul_rn(ay_, vsm[v * 3 + 1])),
                                __fmul_rn(az_, vsm[v * 3 + 2]));
            if (c > best) { best = c; bi = v; }
        }
        out[OFF7 + (size_t)b * NS + s] = (float)bi;

        float tx0 = -vx, tx1 = -vy, tx2 = -vz;
        float ay0 = -tx1, ay1 = tx0, ay2 = 0.f;
        float s2 = ay0 * ay0 + ay1 * ay1;
        if (s2 == 0.f) { ay0 = 0.f; ay1 = 1.f; ay2 = 0.f; }
        float an = sqrtf(tx0 * tx0 + tx1 * tx1 + tx2 * tx2);
        float nx0 = tx0 / an, nx1 = tx1 / an, nx2 = tx2 / an;
        float bn = sqrtf(ay0 * ay0 + ay1 * ay1 + ay2 * ay2);
        float ny0 = ay0 / bn, ny1 = ay1 / bn, ny2 = ay2 / bn;
        float nz0 = nx1 * ny2 - nx2 * ny1;
        float nz1 = nx2 * ny0 - nx0 * ny2;
        float nz2 = nx0 * ny1 - nx1 * ny0;
        size_t base = OFF8 + ((size_t)b * NS + s) * 9;
        out[base + 0] = nx0; out[base + 1] = ny0; out[base + 2] = nz0;
        out[base + 3] = nx1; out[base + 4] = ny1; out[base + 5] = nz1;
        out[base + 6] = nx2; out[base + 7] = ny2; out[base + 8] = nz2;
    }
}

// ================= launch (robust input-order detection) =================
extern "C" void kernel_launch(void* const* d_in, const int* in_sizes, int n_in,
                              void* d_out, int out_size) {
    const float *xyz, *F, *w1, *b1, *gg, *be, *mm, *vv, *w2, *b2;
    const float *c1w, *c1b, *bng, *bnb, *bnm, *bnv, *c2w, *c2b;

    int imax = 0;
    for (int i = 1; i < n_in; ++i)
        if (in_sizes[i] > in_sizes[imax]) imax = i;

    if (imax == 1) {  // dict-insertion / signature order
        xyz = (const float*)d_in[0];  F   = (const float*)d_in[1];
        w1  = (const float*)d_in[2];  b1  = (const float*)d_in[3];
        gg  = (const float*)d_in[4];  be  = (const float*)d_in[5];
        mm  = (const float*)d_in[6];  vv  = (const float*)d_in[7];
        w2  = (const float*)d_in[8];  b2  = (const float*)d_in[9];
        c1w = (const float*)d_in[10]; c1b = (const float*)d_in[11];
        bng = (const float*)d_in[12]; bnb = (const float*)d_in[13];
        bnm = (const float*)d_in[14]; bnv = (const float*)d_in[15];
        c2w = (const float*)d_in[16]; c2b = (const float*)d_in[17];
    } else {          // alphabetical order
        bnb = (const float*)d_in[0];  bng = (const float*)d_in[1];
        bnm = (const float*)d_in[2];  bnv = (const float*)d_in[3];
        c1b = (const float*)d_in[4];  c1w = (const float*)d_in[5];
        c2b = (const float*)d_in[6];  c2w = (const float*)d_in[7];
        b1  = (const float*)d_in[8];  b2  = (const float*)d_in[9];
        be  = (const float*)d_in[10]; gg  = (const float*)d_in[11];
        mm  = (const float*)d_in[12]; vv  = (const float*)d_in[13];
        w1  = (const float*)d_in[14]; w2  = (const float*)d_in[15];
        F   = (const float*)d_in[16]; xyz = (const float*)d_in[17];
    }
    float* out = (float*)d_out;

    const int SM1 = SM1_FLOATS * 4;
    const int SM3 = FP_BYTES;
    const int SM4 = SM4_FLOATS * 4;
    cudaFuncSetAttribute(k_gemm_mask, cudaFuncAttributeMaxDynamicSharedMemorySize, SM1);
    cudaFuncSetAttribute(k_fps, cudaFuncAttributeMaxDynamicSharedMemorySize, SM3);
    cudaFuncSetAttribute(k_view, cudaFuncAttributeMaxDynamicSharedMemorySize, SM4);

    k_prep<<<256, 256>>>(w1, c1w);
    dim3 g1((Np + TPTS - 1) / TPTS, Bb);
    k_gemm_mask<<<g1, 256, SM1>>>(F, b1, gg, be, mm, vv, w2, b2, out);
    k_fps<<<Bb, FT, SM3>>>(xyz, out);
    k_gather<<<Bb * Cc * NS / 256, 256>>>(F, out);
    dim3 g4(NS / TPTS, Bb);
    k_view<<<g4, 256, SM4>>>(c1b, bng, bnb, bnm, bnv, c2w, c2b, out);
}